// round 15
// baseline (speedup 1.0000x reference)
// O3onO2 tensor product — fp32 SIMT, f32x2 FMAs, TILE_M=32, 2 CTAs/SM.
// v15 = v6 (proven) + ONE change: li>=2 combine reads x via per-warp dense
// float4-staged scratch (kills 7-line strided LDG replays). z writes, GEMM,
// W-stage, epilogue byte-identical to v6 (611us baseline).
#include <cuda_runtime.h>
#include <cstdint>

#define NROWS    65536
#define TILE_M   32
#define NTHREADS 256
#define W_STRIDE 66
#define Z_STRIDE 34
#define W_OFF    0
#define Z_OFF    4224                       // 64*66 floats for W
#define SCR_OFF  (Z_OFF + 64 * 7 * Z_STRIDE)      // 19456
#define SCR_W    224                        // floats per warp scratch (max WD)
#define SMEM_FLOATS (SCR_OFF + 8 * SCR_W)   // 21248
#define SMEM_BYTES  (SMEM_FLOATS * 4)       // 84992 B -> 2 CTAs/SM

__device__ __forceinline__ constexpr int blk_off(int l) {
    return l == 0 ? 0 : (l == 1 ? 64 : (l == 2 ? 256 : 576));
}

__device__ __forceinline__ unsigned long long dup2(float a) {
    unsigned long long r;
    asm("mov.b64 %0, {%1, %1};" : "=l"(r) : "f"(a));
    return r;
}
__device__ __forceinline__ void fma2(unsigned long long& d,
                                     unsigned long long a,
                                     unsigned long long b) {
    asm("fma.rn.f32x2 %0, %1, %2, %0;" : "+l"(d) : "l"(a), "l"(b));
}

// ---- stage W transposed (v6): ws[i*66 + o] = W[o][i] ----
template <int LO, int LI>
__device__ __forceinline__ void stage_w(float* __restrict__ sm,
                                        const float* __restrict__ wts) {
    const float* gw = wts + (LO * 4 + LI) * 4096;
    const int tid = threadIdx.x;
#pragma unroll
    for (int s = 0; s < 16; s++) {
        const int idx = tid + s * NTHREADS;
        const int o = idx >> 6, i = idx & 63;
        sm[W_OFF + i * W_STRIDE + o] = __ldg(gw + idx);
    }
}

// ---- v6 combine (direct from global) — used for li = 0,1 ----
template <int LO, int LI>
__device__ __forceinline__ void combine_direct(
    float* __restrict__ sm, const float* __restrict__ gx,
    const float* __restrict__ hz, const float* __restrict__ hpg,
    const float* __restrict__ hng)
{
    constexpr int W21 = 2 * LI + 1;
    constexpr int MM  = LO < LI ? LO : LI;
    constexpr int NZ  = 2 * MM + 1;
    constexpr int P   = LO * 4 + LI;
    const int tid = threadIdx.x;
    const float h0 = __ldg(hz + P);
    float hp[MM ? MM : 1], hn[MM ? MM : 1];
#pragma unroll
    for (int m = 0; m < MM; m++) {
        hp[m] = __ldg(hpg + P * 3 + m);
        hn[m] = __ldg(hng + P * 3 + m);
    }
    float* zs = sm + Z_OFF;
#pragma unroll
    for (int s = 0; s < (64 * TILE_M) / NTHREADS; s++) {
        const int it = tid + s * NTHREADS;
        const int k = it & 63;
        const int r = it >> 6;
        const float* xb = gx + (size_t)r * 1024 + k * W21 + LI;
        float* zcol = zs + (k * NZ) * Z_STRIDE + r;
        zcol[0] = h0 * __ldg(xb);
#pragma unroll
        for (int m = 1; m <= MM; m++) {
            const float xp = __ldg(xb + m);
            const float xn = __ldg(xb - m);
            zcol[(2 * m - 1) * Z_STRIDE] = hp[m - 1] * xp + hn[m - 1] * xn;
            zcol[(2 * m) * Z_STRIDE]     = hp[m - 1] * xn - hn[m - 1] * xp;
        }
    }
}

// ---- staged combine (li = 2,3): identical math/z-writes to combine_direct;
// ONLY the x reads go through a per-warp dense-staged scratch.
// v6 mapping facts: per warp, r = (w>>1)+4s is constant per iteration and
// k = (w&1)*32 + lane is a contiguous 32-k half-range.
template <int LO, int LI>
__device__ __forceinline__ void combine_staged(
    float* __restrict__ sm, const float* __restrict__ gx,
    const float* __restrict__ hz, const float* __restrict__ hpg,
    const float* __restrict__ hng)
{
    constexpr int W21 = 2 * LI + 1;
    constexpr int MM  = LO < LI ? LO : LI;
    constexpr int NZ  = 2 * MM + 1;
    constexpr int P   = LO * 4 + LI;
    constexpr int WD  = 32 * W21;           // slice width in floats
    constexpr int NF4 = WD / 4;             // float4 per slice (40 / 56)
    const int tid  = threadIdx.x;
    const int w    = tid >> 5;
    const int lane = tid & 31;
    const int kw   = (w & 1) * 32;
    const int k    = kw + lane;
    const float h0 = __ldg(hz + P);
    float hp[MM ? MM : 1], hn[MM ? MM : 1];
#pragma unroll
    for (int m = 0; m < MM; m++) {
        hp[m] = __ldg(hpg + P * 3 + m);
        hn[m] = __ldg(hng + P * 3 + m);
    }
    float* scr = sm + SCR_OFF + w * SCR_W;
    float4* scr4 = reinterpret_cast<float4*>(scr);
    float* zs = sm + Z_OFF;
#pragma unroll
    for (int s = 0; s < (64 * TILE_M) / NTHREADS; s++) {
        const int r = (w >> 1) + s * 4;     // same r as v6's it>>6 for this warp
        __syncwarp();                       // prior iteration's reads complete
        const float4* g = reinterpret_cast<const float4*>(
            gx + (size_t)r * 1024 + kw * W21);
        for (int u = lane; u < NF4; u += 32) scr4[u] = __ldg(g + u);
        __syncwarp();
        const float* xb = scr + lane * W21 + LI;   // == col k*W21+LI - kw*W21
        float* zcol = zs + (k * NZ) * Z_STRIDE + r;
        zcol[0] = h0 * xb[0];
#pragma unroll
        for (int m = 1; m <= MM; m++) {
            const float xp = xb[m];
            const float xn = xb[-m];
            zcol[(2 * m - 1) * Z_STRIDE] = hp[m - 1] * xp + hn[m - 1] * xn;
            zcol[(2 * m) * Z_STRIDE]     = hp[m - 1] * xn - hn[m - 1] * xp;
        }
    }
}

// ---- GEMM (v6): warp rg = row pairs rg, rg+8; lane og = 2 out channels ----
template <int LO, int LI>
__device__ __forceinline__ void gemm(
    const float* __restrict__ sm,
    unsigned long long (&acc)[2][2][2 * LO + 1], int rg, int og)
{
    constexpr int MM = LO < LI ? LO : LI;
    constexpr int NZ = 2 * MM + 1;
    const unsigned long long* zb =
        reinterpret_cast<const unsigned long long*>(sm + Z_OFF);
    const float* wsl = sm + W_OFF + og * 2;
#pragma unroll 4
    for (int k = 0; k < 64; k++) {
        const float2 wv = *reinterpret_cast<const float2*>(wsl + k * W_STRIDE);
        const unsigned long long w0 = dup2(wv.x);
        const unsigned long long w1 = dup2(wv.y);
#pragma unroll
        for (int zc = 0; zc < NZ; zc++) {
            const int c = (zc == 0) ? LO
                         : ((zc & 1) ? LO + (zc + 1) / 2 : LO - zc / 2);
            const int col = k * NZ + zc;
            const unsigned long long zA = zb[col * (Z_STRIDE / 2) + rg];
            const unsigned long long zB = zb[col * (Z_STRIDE / 2) + rg + 8];
            fma2(acc[0][0][c], zA, w0);
            fma2(acc[0][1][c], zA, w1);
            fma2(acc[1][0][c], zB, w0);
            fma2(acc[1][1][c], zB, w1);
        }
    }
}

template <int LO>
__device__ __forceinline__ void run(
    float* __restrict__ sm, const float* __restrict__ x,
    const float* __restrict__ wts, const float* __restrict__ hz,
    const float* __restrict__ hpg, const float* __restrict__ hng,
    float* __restrict__ out, int tile)
{
    constexpr int NC  = 2 * LO + 1;
    constexpr int SEG = 64 * NC;
    constexpr int NQ  = SEG / 4;
    const int tid = threadIdx.x;
    const int rg  = tid >> 5;
    const int og  = tid & 31;
    const float* gx = x + (size_t)tile * TILE_M * 1024;

    unsigned long long acc[2][2][NC];
#pragma unroll
    for (int a = 0; a < 2; a++)
#pragma unroll
        for (int b = 0; b < 2; b++)
#pragma unroll
            for (int c = 0; c < NC; c++) acc[a][b][c] = 0ull;

    stage_w<LO, 0>(sm, wts);
    combine_direct<LO, 0>(sm, gx + blk_off(0), hz, hpg, hng);
    __syncthreads();
    gemm<LO, 0>(sm, acc, rg, og);
    __syncthreads();
    stage_w<LO, 1>(sm, wts);
    combine_direct<LO, 1>(sm, gx + blk_off(1), hz, hpg, hng);
    __syncthreads();
    gemm<LO, 1>(sm, acc, rg, og);
    __syncthreads();
    stage_w<LO, 2>(sm, wts);
    combine_staged<LO, 2>(sm, gx + blk_off(2), hz, hpg, hng);
    __syncthreads();
    gemm<LO, 2>(sm, acc, rg, og);
    __syncthreads();
    stage_w<LO, 3>(sm, wts);
    combine_staged<LO, 3>(sm, gx + blk_off(3), hz, hpg, hng);
    __syncthreads();
    gemm<LO, 3>(sm, acc, rg, og);

    // ---- output: stage tile in smem (global layout), coalesced f4 stores ----
    __syncthreads();                      // everyone done reading z
    float* smo = sm + Z_OFF;
#pragma unroll
    for (int pr = 0; pr < 2; pr++) {
        const int rbase = 2 * (rg + pr * 8);
#pragma unroll
        for (int oo = 0; oo < 2; oo++) {
            const int o = og * 2 + oo;
#pragma unroll
            for (int c = 0; c < NC; c++) {
                const unsigned long long v = acc[pr][oo][c];
                smo[rbase * SEG + o * NC + c] =
                    __uint_as_float((unsigned)(v & 0xffffffffu));
                smo[(rbase + 1) * SEG + o * NC + c] =
                    __uint_as_float((unsigned)(v >> 32));
            }
        }
    }
    __syncthreads();
    float* go = out + (size_t)tile * TILE_M * 1024 + blk_off(LO);
#pragma unroll
    for (int rr = 0; rr < TILE_M / 8; rr++) {
        const int r = rg * (TILE_M / 8) + rr;
        for (int j = og; j < NQ; j += 32) {
            *reinterpret_cast<float4*>(go + (size_t)r * 1024 + j * 4) =
                *reinterpret_cast<const float4*>(smo + r * SEG + j * 4);
        }
    }
}

extern "C" __global__ void __launch_bounds__(NTHREADS, 2)
tp_kernel(const float* __restrict__ x, const float* __restrict__ wts,
          const float* __restrict__ hz, const float* __restrict__ hpg,
          const float* __restrict__ hng, float* __restrict__ out)
{
    extern __shared__ float sm[];
    const int tile = blockIdx.y;
    switch (blockIdx.x) {
        case 0: run<0>(sm, x, wts, hz, hpg, hng, out, tile); break;
        case 1: run<1>(sm, x, wts, hz, hpg, hng, out, tile); break;
        case 2: run<2>(sm, x, wts, hz, hpg, hng, out, tile); break;
        default: run<3>(sm, x, wts, hz, hpg, hng, out, tile); break;
    }
}

extern "C" void kernel_launch(void* const* d_in, const int* in_sizes, int n_in,
                              void* d_out, int out_size)
{
    const float* x   = (const float*)d_in[0];
    const float* wts = (const float*)d_in[1];
    const float* hz  = (const float*)d_in[2];
    const float* hpg = (const float*)d_in[3];
    const float* hng = (const float*)d_in[4];
    float* out = (float*)d_out;

    cudaFuncSetAttribute(tp_kernel, cudaFuncAttributeMaxDynamicSharedMemorySize,
                         SMEM_BYTES);
    dim3 grid(4, NROWS / TILE_M);
    tp_kernel<<<grid, NTHREADS, SMEM_BYTES>>>(x, wts, hz, hpg, hng, out);
}

// round 17
// speedup vs baseline: 1.1074x; 1.1074x over previous
// O3onO2 tensor product — fp32 SIMT, f32x2 FMAs, TILE_M=32, 2 CTAs/SM.
// v16 = v6 algorithm with 512 threads/CTA: warp = row-pair, lane = 2 out-ch,
// acc[2][NC] (<=28 regs) -> 64-reg cap -> 32 warps/SM (2x latency hiding).
#include <cuda_runtime.h>
#include <cstdint>

#define NROWS    65536
#define TILE_M   32
#define NTHREADS 512
#define W_STRIDE 66
#define Z_STRIDE 34
#define W_OFF    0
#define Z_OFF    4224                       // 64*66 floats for W
#define SMEM_FLOATS (Z_OFF + 64 * 7 * Z_STRIDE)   // 4224 + 15232 = 19456
#define SMEM_BYTES  (SMEM_FLOATS * 4)             // 77824 B -> 2 CTAs/SM

__device__ __forceinline__ constexpr int blk_off(int l) {
    return l == 0 ? 0 : (l == 1 ? 64 : (l == 2 ? 256 : 576));
}

__device__ __forceinline__ unsigned long long dup2(float a) {
    unsigned long long r;
    asm("mov.b64 %0, {%1, %1};" : "=l"(r) : "f"(a));
    return r;
}
__device__ __forceinline__ void fma2(unsigned long long& d,
                                     unsigned long long a,
                                     unsigned long long b) {
    asm("fma.rn.f32x2 %0, %1, %2, %0;" : "+l"(d) : "l"(a), "l"(b));
}

// ---- stage W transposed (v6): ws[i*66 + o] = W[o][i] ----
template <int LO, int LI>
__device__ __forceinline__ void stage_w(float* __restrict__ sm,
                                        const float* __restrict__ wts) {
    const float* gw = wts + (LO * 4 + LI) * 4096;
    const int tid = threadIdx.x;
#pragma unroll
    for (int s = 0; s < 8; s++) {
        const int idx = tid + s * NTHREADS;
        const int o = idx >> 6, i = idx & 63;
        sm[W_OFF + i * W_STRIDE + o] = __ldg(gw + idx);
    }
}

// ---- combine (v6, direct from global), 512-thread mapping ----
template <int LO, int LI>
__device__ __forceinline__ void combine(
    float* __restrict__ sm, const float* __restrict__ gx,
    const float* __restrict__ hz, const float* __restrict__ hpg,
    const float* __restrict__ hng)
{
    constexpr int W21 = 2 * LI + 1;
    constexpr int MM  = LO < LI ? LO : LI;
    constexpr int NZ  = 2 * MM + 1;
    constexpr int P   = LO * 4 + LI;
    const int tid = threadIdx.x;
    const float h0 = __ldg(hz + P);
    float hp[MM ? MM : 1], hn[MM ? MM : 1];
#pragma unroll
    for (int m = 0; m < MM; m++) {
        hp[m] = __ldg(hpg + P * 3 + m);
        hn[m] = __ldg(hng + P * 3 + m);
    }
    float* zs = sm + Z_OFF;
#pragma unroll
    for (int s = 0; s < (64 * TILE_M) / NTHREADS; s++) {
        const int it = tid + s * NTHREADS;
        const int k = it & 63;
        const int r = it >> 6;
        const float* xb = gx + (size_t)r * 1024 + k * W21 + LI;
        float* zcol = zs + (k * NZ) * Z_STRIDE + r;
        zcol[0] = h0 * __ldg(xb);
#pragma unroll
        for (int m = 1; m <= MM; m++) {
            const float xp = __ldg(xb + m);
            const float xn = __ldg(xb - m);
            zcol[(2 * m - 1) * Z_STRIDE] = hp[m - 1] * xp + hn[m - 1] * xn;
            zcol[(2 * m) * Z_STRIDE]     = hp[m - 1] * xn - hn[m - 1] * xp;
        }
    }
}

// ---- GEMM: warp = row pair rp, lane og = 2 out channels ----
template <int LO, int LI>
__device__ __forceinline__ void gemm(
    const float* __restrict__ sm,
    unsigned long long (&acc)[2][2 * LO + 1], int rp, int og)
{
    constexpr int MM = LO < LI ? LO : LI;
    constexpr int NZ = 2 * MM + 1;
    const unsigned long long* zb =
        reinterpret_cast<const unsigned long long*>(sm + Z_OFF);
    const float* wsl = sm + W_OFF + og * 2;
#pragma unroll 4
    for (int k = 0; k < 64; k++) {
        const float2 wv = *reinterpret_cast<const float2*>(wsl + k * W_STRIDE);
        const unsigned long long w0 = dup2(wv.x);
        const unsigned long long w1 = dup2(wv.y);
#pragma unroll
        for (int zc = 0; zc < NZ; zc++) {
            const int c = (zc == 0) ? LO
                         : ((zc & 1) ? LO + (zc + 1) / 2 : LO - zc / 2);
            const unsigned long long z =
                zb[(k * NZ + zc) * (Z_STRIDE / 2) + rp];
            fma2(acc[0][c], z, w0);
            fma2(acc[1][c], z, w1);
        }
    }
}

template <int LO>
__device__ __forceinline__ void run(
    float* __restrict__ sm, const float* __restrict__ x,
    const float* __restrict__ wts, const float* __restrict__ hz,
    const float* __restrict__ hpg, const float* __restrict__ hng,
    float* __restrict__ out, int tile)
{
    constexpr int NC  = 2 * LO + 1;
    constexpr int SEG = 64 * NC;
    constexpr int NQ  = SEG / 4;
    const int tid = threadIdx.x;
    const int rp  = tid >> 5;               // warp id = row pair 0..15
    const int og  = tid & 31;               // lane = 2 out channels
    const float* gx = x + (size_t)tile * TILE_M * 1024;

    unsigned long long acc[2][NC];
#pragma unroll
    for (int a = 0; a < 2; a++)
#pragma unroll
        for (int c = 0; c < NC; c++) acc[a][c] = 0ull;

    stage_w<LO, 0>(sm, wts);
    combine<LO, 0>(sm, gx + blk_off(0), hz, hpg, hng);
    __syncthreads();
    gemm<LO, 0>(sm, acc, rp, og);
    __syncthreads();
    stage_w<LO, 1>(sm, wts);
    combine<LO, 1>(sm, gx + blk_off(1), hz, hpg, hng);
    __syncthreads();
    gemm<LO, 1>(sm, acc, rp, og);
    __syncthreads();
    stage_w<LO, 2>(sm, wts);
    combine<LO, 2>(sm, gx + blk_off(2), hz, hpg, hng);
    __syncthreads();
    gemm<LO, 2>(sm, acc, rp, og);
    __syncthreads();
    stage_w<LO, 3>(sm, wts);
    combine<LO, 3>(sm, gx + blk_off(3), hz, hpg, hng);
    __syncthreads();
    gemm<LO, 3>(sm, acc, rp, og);

    // ---- output: stage tile in smem (global layout), coalesced f4 stores ----
    __syncthreads();                      // everyone done reading z
    float* smo = sm + Z_OFF;
    const int r0 = rp * 2;
#pragma unroll
    for (int oo = 0; oo < 2; oo++) {
        const int o = og * 2 + oo;
#pragma unroll
        for (int c = 0; c < NC; c++) {
            const unsigned long long v = acc[oo][c];
            smo[r0 * SEG + o * NC + c] =
                __uint_as_float((unsigned)(v & 0xffffffffu));
            smo[(r0 + 1) * SEG + o * NC + c] =
                __uint_as_float((unsigned)(v >> 32));
        }
    }
    __syncthreads();
    float* go = out + (size_t)tile * TILE_M * 1024 + blk_off(LO);
#pragma unroll
    for (int rr = 0; rr < 2; rr++) {
        const int r = rp * 2 + rr;
        for (int j = og; j < NQ; j += 32) {
            *reinterpret_cast<float4*>(go + (size_t)r * 1024 + j * 4) =
                *reinterpret_cast<const float4*>(smo + r * SEG + j * 4);
        }
    }
}

extern "C" __global__ void __launch_bounds__(NTHREADS, 2)
tp_kernel(const float* __restrict__ x, const float* __restrict__ wts,
          const float* __restrict__ hz, const float* __restrict__ hpg,
          const float* __restrict__ hng, float* __restrict__ out)
{
    extern __shared__ float sm[];
    const int tile = blockIdx.y;
    switch (blockIdx.x) {
        case 0: run<0>(sm, x, wts, hz, hpg, hng, out, tile); break;
        case 1: run<1>(sm, x, wts, hz, hpg, hng, out, tile); break;
        case 2: run<2>(sm, x, wts, hz, hpg, hng, out, tile); break;
        default: run<3>(sm, x, wts, hz, hpg, hng, out, tile); break;
    }
}

extern "C" void kernel_launch(void* const* d_in, const int* in_sizes, int n_in,
                              void* d_out, int out_size)
{
    const float* x   = (const float*)d_in[0];
    const float* wts = (const float*)d_in[1];
    const float* hz  = (const float*)d_in[2];
    const float* hpg = (const float*)d_in[3];
    const float* hng = (const float*)d_in[4];
    float* out = (float*)d_out;

    cudaFuncSetAttribute(tp_kernel, cudaFuncAttributeMaxDynamicSharedMemorySize,
                         SMEM_BYTES);
    dim3 grid(4, NROWS / TILE_M);
    tp_kernel<<<grid, NTHREADS, SMEM_BYTES>>>(x, wts, hz, hpg, hng, out);
}